// round 8
// baseline (speedup 1.0000x reference)
#include <cuda_runtime.h>
#include <cstdint>

// out_i = sign(x) * u_i / ||u||, u = W[0,1:4]; 0 when x == 0.
// Hybrid path: input via plain LDG (cheap issue, latency hidden by warps),
// output via STS -> cp.async.bulk smem->global (removes ~8k cyc/SM of
// STG.128 LSU issue cost). 2048 independent CTAs, 24KB smem, ~9 CTAs/SM.

#define HWPIX   (512 * 512)
#define NBATCH  16
#define TILE    2048                 // elements per CTA
#define TILE_B  (TILE * 4)           // 8KB per plane
#define THREADS 256
#define SMEM_BYTES (3 * TILE_B)      // 24KB

__global__ __launch_bounds__(THREADS) void scene_normal_kernel(
    const float* __restrict__ depth,    // [16*512*512]
    const float* __restrict__ Wm,       // [8,8]
    float* __restrict__ out)            // [16,3,512,512]
{
    __shared__ alignas(128) float s_out[3][TILE];

    const int tid  = threadIdx.x;
    const int n0   = blockIdx.x * TILE;       // block-contiguous chunk
    const int b    = n0 >> 18;                // TILE divides HWPIX
    const int rem0 = n0 & (HWPIX - 1);

    const float u1 = Wm[1];
    const float u2 = Wm[2];
    const float u3 = Wm[3];
    const float r  = rsqrtf(u1 * u1 + u2 * u2 + u3 * u3);
    const float c1 = u1 * r, c2 = u2 * r, c3 = u3 * r;

    const float4* in4 = reinterpret_cast<const float4*>(depth + n0) + tid;
    float4* o0 = reinterpret_cast<float4*>(s_out[0]) + tid;
    float4* o1 = reinterpret_cast<float4*>(s_out[1]) + tid;
    float4* o2 = reinterpret_cast<float4*>(s_out[2]) + tid;

#pragma unroll
    for (int i = 0; i < TILE / 4 / THREADS; i++) {   // 2 iters
        const float4 x = __ldg(in4 + i * THREADS);
        const float s0 = (x.x > 0.f) ? 1.f : ((x.x < 0.f) ? -1.f : 0.f);
        const float s1 = (x.y > 0.f) ? 1.f : ((x.y < 0.f) ? -1.f : 0.f);
        const float s2 = (x.z > 0.f) ? 1.f : ((x.z < 0.f) ? -1.f : 0.f);
        const float s3 = (x.w > 0.f) ? 1.f : ((x.w < 0.f) ? -1.f : 0.f);
        o0[i * THREADS] = make_float4(s0 * c1, s1 * c1, s2 * c1, s3 * c1);
        o1[i * THREADS] = make_float4(s0 * c2, s1 * c2, s2 * c2, s3 * c2);
        o2[i * THREADS] = make_float4(s0 * c3, s1 * c3, s2 * c3, s3 * c3);
    }
    __syncthreads();

    if (tid == 0) {
        asm volatile("fence.proxy.async.shared::cta;" ::: "memory");
        float* dst = out + (size_t)b * 3 * HWPIX + rem0;
#pragma unroll
        for (int pln = 0; pln < 3; pln++) {
            const uint32_t so = (uint32_t)__cvta_generic_to_shared(s_out[pln]);
            asm volatile(
                "cp.async.bulk.global.shared::cta.bulk_group [%0], [%1], %2;"
                :: "l"(dst + (size_t)pln * HWPIX), "r"(so), "r"(TILE_B)
                : "memory");
        }
        asm volatile("cp.async.bulk.commit_group;" ::: "memory");
        asm volatile("cp.async.bulk.wait_group 0;" ::: "memory");
    }
    // Other threads exit; CTA (and its smem) stays alive until tid0's wait
    // completes, so the bulk stores read valid smem.
}

extern "C" void kernel_launch(void* const* d_in, const int* in_sizes, int n_in,
                              void* d_out, int out_size)
{
    const float* depth = (const float*)d_in[0];
    const float* Wm    = (const float*)d_in[1];
    float* out         = (float*)d_out;

    const int blocks = (NBATCH * HWPIX) / TILE;   // 2048

    scene_normal_kernel<<<blocks, THREADS>>>(depth, Wm, out);
}

// round 9
// speedup vs baseline: 1.0025x; 1.0025x over previous
#include <cuda_runtime.h>
#include <cstdint>

// out_i = sign(x) * u_i / ||u||, u = W[0,1:4]; 0 when x == 0.
// TMA bulk loads (bypass the ~8KB/SM LDG outstanding-miss cap) with ALL of a
// CTA's tiles issued up front into distinct buffers -> zero loop barriers,
// zero buffer reuse. Stores are plain STG.128 from registers.

#define HWPIX    (512 * 512)
#define NBATCH   16
#define TILE     4096                  // elements per tile (16KB)
#define TILE_B   (TILE * 4)
#define NTILES   ((NBATCH * HWPIX) / TILE)   // 1024
#define GRID     296                   // 2 CTAs/SM, single wave
#define THREADS  512
#define MAXT     4                     // max tiles per CTA (ceil(1024/296))
#define SMEM_BYTES (MAXT * TILE_B)     // 64KB

__device__ __forceinline__ void mbar_wait0(uint32_t mbar_a) {
    uint32_t done;
    asm volatile(
        "{\n\t.reg .pred p;\n\t"
        "mbarrier.try_wait.parity.acquire.cta.shared::cta.b64 p, [%1], 0;\n\t"
        "selp.b32 %0, 1, 0, p;\n\t}"
        : "=r"(done) : "r"(mbar_a) : "memory");
    if (!done) {
        asm volatile(
            "{\n\t.reg .pred P1;\n\t"
            "WAIT_LOOP_%=:\n\t"
            "mbarrier.try_wait.parity.acquire.cta.shared::cta.b64 P1, [%0], 0, 0x989680;\n\t"
            "@P1 bra.uni WAIT_DONE_%=;\n\t"
            "bra.uni WAIT_LOOP_%=;\n\t"
            "WAIT_DONE_%=:\n\t}"
            :: "r"(mbar_a) : "memory");
    }
}

__global__ __launch_bounds__(THREADS) void scene_normal_kernel(
    const float* __restrict__ depth,    // [16*512*512]
    const float* __restrict__ Wm,       // [8,8]
    float* __restrict__ out)            // [16,3,512,512]
{
    extern __shared__ float s_in[];     // [MAXT][TILE]
    __shared__ alignas(8) unsigned long long mbar[MAXT];

    const int tid = threadIdx.x;
    const int bid = blockIdx.x;

    // tiles this CTA owns: t = bid + j*GRID, j < nt
    const int nt = (NTILES - bid + GRID - 1) / GRID;   // 3 or 4

    uint32_t mbar_a[MAXT];
#pragma unroll
    for (int s = 0; s < MAXT; s++)
        mbar_a[s] = (uint32_t)__cvta_generic_to_shared(&mbar[s]);

    if (tid == 0) {
#pragma unroll
        for (int s = 0; s < MAXT; s++)
            asm volatile("mbarrier.init.shared.b64 [%0], 1;" :: "r"(mbar_a[s]) : "memory");
    }
    __syncthreads();   // mbarrier init visible before TMA targets them

    // Issue ALL loads up front: ~nt*16KB in flight per CTA immediately.
    if (tid == 0) {
#pragma unroll
        for (int j = 0; j < MAXT; j++) {
            if (j < nt) {
                const int t = bid + j * GRID;
                const uint32_t dst = (uint32_t)__cvta_generic_to_shared(s_in + j * TILE);
                asm volatile("mbarrier.arrive.expect_tx.shared.b64 _, [%0], %1;"
                             :: "r"(mbar_a[j]), "r"(TILE_B) : "memory");
                asm volatile(
                    "cp.async.bulk.shared::cluster.global.mbarrier::complete_tx::bytes "
                    "[%0], [%1], %2, [%3];"
                    :: "r"(dst), "l"(depth + (size_t)t * TILE), "r"(TILE_B), "r"(mbar_a[j])
                    : "memory");
            }
        }
    }

    // Constants while loads fly.
    const float u1 = Wm[1];
    const float u2 = Wm[2];
    const float u3 = Wm[3];
    const float r  = rsqrtf(u1 * u1 + u2 * u2 + u3 * u3);
    const float c1 = u1 * r, c2 = u2 * r, c3 = u3 * r;

    for (int j = 0; j < nt; j++) {
        const int t   = bid + j * GRID;
        const int n0  = t * TILE;
        const int b   = n0 >> 18;             // TILE divides HWPIX
        const int rem = n0 & (HWPIX - 1);

        mbar_wait0(mbar_a[j]);                // per-thread wait, no CTA barrier

        const float4* in4 = reinterpret_cast<const float4*>(s_in + j * TILE) + tid;
        float* dst = out + (size_t)b * 3 * HWPIX + rem;
        float4* d0 = reinterpret_cast<float4*>(dst) + tid;
        float4* d1 = reinterpret_cast<float4*>(dst + HWPIX) + tid;
        float4* d2 = reinterpret_cast<float4*>(dst + 2 * HWPIX) + tid;

#pragma unroll
        for (int i = 0; i < TILE / 4 / THREADS; i++) {   // 2 iters
            const float4 x = in4[i * THREADS];
            const float s0 = (x.x > 0.f) ? 1.f : ((x.x < 0.f) ? -1.f : 0.f);
            const float s1 = (x.y > 0.f) ? 1.f : ((x.y < 0.f) ? -1.f : 0.f);
            const float s2 = (x.z > 0.f) ? 1.f : ((x.z < 0.f) ? -1.f : 0.f);
            const float s3 = (x.w > 0.f) ? 1.f : ((x.w < 0.f) ? -1.f : 0.f);
            d0[i * THREADS] = make_float4(s0 * c1, s1 * c1, s2 * c1, s3 * c1);
            d1[i * THREADS] = make_float4(s0 * c2, s1 * c2, s2 * c2, s3 * c2);
            d2[i * THREADS] = make_float4(s0 * c3, s1 * c3, s2 * c3, s3 * c3);
        }
    }
}

extern "C" void kernel_launch(void* const* d_in, const int* in_sizes, int n_in,
                              void* d_out, int out_size)
{
    const float* depth = (const float*)d_in[0];
    const float* Wm    = (const float*)d_in[1];
    float* out         = (float*)d_out;

    cudaFuncSetAttribute(scene_normal_kernel,
                         cudaFuncAttributeMaxDynamicSharedMemorySize, SMEM_BYTES);

    scene_normal_kernel<<<GRID, THREADS, SMEM_BYTES>>>(depth, Wm, out);
}

// round 10
// speedup vs baseline: 1.0201x; 1.0175x over previous
#include <cuda_runtime.h>

// out_i = sign(x) * u_i / ||u||, u = W[0,1:4]; 0 when x == 0.
// Final form: the mandatory traffic (16MB read + 48MB write) is LTS/clock
// bound in steady state; simplest single-wave LDG/STG shape measured fastest.
// 1024 CTAs x 256 thr, 4 float4/thread, load interleaved with its stores so
// the write stream starts immediately and the tail drains minimally.

#define HWPIX (512 * 512)            // 2^18 elements per plane
#define NBATCH 16
#define F4_PER_THREAD 4
#define THREADS 256
#define BLOCK_ELEMS (THREADS * F4_PER_THREAD * 4)   // 4096

__global__ __launch_bounds__(THREADS) void scene_normal_kernel(
    const float4* __restrict__ depth4,   // [16*512*512/4]
    const float*  __restrict__ Wm,       // [8,8] row-major
    float* __restrict__ out)             // [16,3,512,512] flat
{
    const float u1 = Wm[1];
    const float u2 = Wm[2];
    const float u3 = Wm[3];
    const float r  = rsqrtf(u1 * u1 + u2 * u2 + u3 * u3);
    const float c1 = u1 * r, c2 = u2 * r, c3 = u3 * r;

    const int n0   = blockIdx.x * BLOCK_ELEMS;   // block-contiguous chunk
    const int b    = n0 >> 18;                   // HWPIX | BLOCK_ELEMS*64
    const int rem0 = n0 & (HWPIX - 1);

    const float4* __restrict__ in4 = depth4 + (n0 >> 2) + threadIdx.x;
    float* basep = out + (size_t)b * 3 * HWPIX + rem0;
    float4* __restrict__ o1 = reinterpret_cast<float4*>(basep) + threadIdx.x;
    float4* __restrict__ o2 = reinterpret_cast<float4*>(basep + HWPIX) + threadIdx.x;
    float4* __restrict__ o3 = reinterpret_cast<float4*>(basep + 2 * HWPIX) + threadIdx.x;

    // Stage the first load, then per iteration: kick next load, store current.
    float4 x = in4[0];

#pragma unroll
    for (int i = 0; i < F4_PER_THREAD; i++) {
        float4 xn;
        if (i + 1 < F4_PER_THREAD)
            xn = in4[(i + 1) * THREADS];     // next load in flight over stores

        const float s0 = (x.x > 0.f) ? 1.f : ((x.x < 0.f) ? -1.f : 0.f);
        const float s1 = (x.y > 0.f) ? 1.f : ((x.y < 0.f) ? -1.f : 0.f);
        const float s2 = (x.z > 0.f) ? 1.f : ((x.z < 0.f) ? -1.f : 0.f);
        const float s3 = (x.w > 0.f) ? 1.f : ((x.w < 0.f) ? -1.f : 0.f);

        o1[i * THREADS] = make_float4(s0 * c1, s1 * c1, s2 * c1, s3 * c1);
        o2[i * THREADS] = make_float4(s0 * c2, s1 * c2, s2 * c2, s3 * c2);
        o3[i * THREADS] = make_float4(s0 * c3, s1 * c3, s2 * c3, s3 * c3);

        x = xn;
    }
}

extern "C" void kernel_launch(void* const* d_in, const int* in_sizes, int n_in,
                              void* d_out, int out_size)
{
    const float4* depth4 = (const float4*)d_in[0];
    const float*  Wm     = (const float*)d_in[1];
    float* out           = (float*)d_out;

    const int n_elems = NBATCH * HWPIX;          // 4,194,304
    const int blocks  = n_elems / BLOCK_ELEMS;   // 1024 (all resident, one wave)

    scene_normal_kernel<<<blocks, THREADS>>>(depth4, Wm, out);
}